// round 2
// baseline (speedup 1.0000x reference)
#include <cuda_runtime.h>
#include <math_constants.h>

#define D       256
#define NT      65536
#define NE      4096
#define BM      128
#define BN      128
#define BK      16
#define BMP     (BM + 1)   // smem padding: conflict-free transposed stores

__device__ float g_eNormHalf[NE];
__device__ int   g_idx[NT];

// ---------------------------------------------------------------------------
// Kernel 1: 0.5 * ||e||^2 per codebook row. One warp per row.
// ---------------------------------------------------------------------------
__global__ void enorm_kernel(const float* __restrict__ e) {
    int row  = blockIdx.x * (blockDim.x >> 5) + (threadIdx.x >> 5);
    int lane = threadIdx.x & 31;
    if (row >= NE) return;
    const float4* p = (const float4*)(e + row * D);
    float s = 0.f;
    #pragma unroll
    for (int i = lane; i < D / 4; i += 32) {
        float4 v = p[i];
        s += v.x * v.x + v.y * v.y + v.z * v.z + v.w * v.w;
    }
    #pragma unroll
    for (int o = 16; o; o >>= 1) s += __shfl_xor_sync(0xFFFFFFFFu, s, o);
    if (lane == 0) g_eNormHalf[row] = 0.5f * s;
}

// ---------------------------------------------------------------------------
// Kernel 2: fused GEMM + argmin.
// Grid: 512 blocks over M (tokens). Each block owns 128 tokens and sweeps all
// 4096 codes in 32 tiles of 128, keeping the running (score, idx) minimum in
// registers. score = ||e||^2/2 - z.e  (||z||^2 constant per token).
// 256 threads as 16x16; each thread computes an 8x8 register tile.
// ---------------------------------------------------------------------------
__global__ __launch_bounds__(256, 2)
void argmin_kernel(const float* __restrict__ z, const float* __restrict__ e) {
    __shared__ float As[BK][BMP];
    __shared__ float Bs[BK][BMP];
    __shared__ float redS[BM][17];
    __shared__ int   redI[BM][17];

    const int tid = threadIdx.x;
    const int tx  = tid & 15;
    const int ty  = tid >> 4;
    const int m0  = blockIdx.x * BM;

    float bestS[8];
    int   bestI[8];
    #pragma unroll
    for (int i = 0; i < 8; i++) { bestS[i] = CUDART_INF_F; bestI[i] = 0; }

    for (int n0 = 0; n0 < NE; n0 += BN) {
        float acc[8][8];
        #pragma unroll
        for (int i = 0; i < 8; i++)
            #pragma unroll
            for (int j = 0; j < 8; j++) acc[i][j] = 0.f;

        for (int k0 = 0; k0 < D; k0 += BK) {
            // cooperative load: 2048 elements each of A,B; 8 per thread
            #pragma unroll
            for (int r = 0; r < 8; r++) {
                int eidx = tid + r * 256;
                int m    = eidx >> 4;
                int k    = eidx & 15;
                As[k][m] = z[(m0 + m) * D + k0 + k];
                Bs[k][m] = e[(n0 + m) * D + k0 + k];
            }
            __syncthreads();

            #pragma unroll
            for (int k = 0; k < BK; k++) {
                float a[8], b[8];
                #pragma unroll
                for (int i = 0; i < 8; i++) a[i] = As[k][ty + 16 * i];
                #pragma unroll
                for (int j = 0; j < 8; j++) b[j] = Bs[k][tx + 16 * j];
                #pragma unroll
                for (int i = 0; i < 8; i++)
                    #pragma unroll
                    for (int j = 0; j < 8; j++)
                        acc[i][j] += a[i] * b[j];
            }
            __syncthreads();
        }

        // fold this code-tile into the running argmin
        #pragma unroll
        for (int j = 0; j < 8; j++) {
            int   n  = n0 + tx + 16 * j;
            float en = __ldg(&g_eNormHalf[n]);
            #pragma unroll
            for (int i = 0; i < 8; i++) {
                float s = en - acc[i][j];
                if (s < bestS[i]) { bestS[i] = s; bestI[i] = n; }
            }
        }
    }

    // reduce across the 16 tx-threads sharing each token row
    #pragma unroll
    for (int i = 0; i < 8; i++) {
        redS[ty + 16 * i][tx] = bestS[i];
        redI[ty + 16 * i][tx] = bestI[i];
    }
    __syncthreads();
    if (tid < BM) {
        float bs = redS[tid][0];
        int   bi = redI[tid][0];
        #pragma unroll
        for (int t = 1; t < 16; t++) {
            float s = redS[tid][t];
            int   n = redI[tid][t];
            if (s < bs || (s == bs && n < bi)) { bs = s; bi = n; }
        }
        g_idx[m0 + tid] = bi;
    }
}

// ---------------------------------------------------------------------------
// Kernel 3: gather z_quantized = embedding[idx], float4 at a time.
// Optionally writes indices (as float) into the tail of the output buffer.
// ---------------------------------------------------------------------------
__global__ void gather_kernel(const float* __restrict__ e,
                              float* __restrict__ out,
                              int write_idx_tail) {
    int t   = blockIdx.x * blockDim.x + threadIdx.x;   // over NT * (D/4)
    int row = t >> 6;       // D/4 = 64 float4 per row
    int c   = t & 63;
    int idx = g_idx[row];
    ((float4*)out)[t] = ((const float4*)(e + idx * D))[c];
    if (write_idx_tail && c == 0) {
        out[NT * D + row] = (float)idx;
    }
}

extern "C" void kernel_launch(void* const* d_in, const int* in_sizes, int n_in,
                              void* d_out, int out_size) {
    const float* z = (const float*)d_in[0];
    const float* e = (const float*)d_in[1];
    float* out = (float*)d_out;

    int write_idx_tail = (out_size >= NT * D + NT) ? 1 : 0;

    enorm_kernel<<<NE / 8, 256>>>(e);           // 8 rows per 256-thread block
    argmin_kernel<<<NT / BM, 256>>>(z, e);      // 512 blocks
    gather_kernel<<<(NT * (D / 4)) / 256, 256>>>(e, out, write_idx_tail);
}